// round 11
// baseline (speedup 1.0000x reference)
#include <cuda_runtime.h>
#include <cuda_fp16.h>
#include <cstdint>

// ---------------------------------------------------------------------------
// ResidualBlock: y = feat@Wnin + subconv(bnrelu2(subconv(bnrelu1(feat),W1)),W2)
// N=100000, A=64, B=128, K=27. fp32 in/out.
// Engine: mma.sync m16n8k16 fp16 (HMMA), single pass, fp32 accum.
// Round-11: FAT stages (1 per offset), BN hoisted into elementwise prepass,
// pure cp.async double-buffered gather-GEMM (zero staging registers).
// Mask semantics: masked-off rows contribute TRUE zeros (zero-page gather).
// ---------------------------------------------------------------------------

#define KK   27
#define AA   64
#define BB   128
#define NMAX 100000
#define PB   512

// ---------------- static device scratch ------------------------------------
__device__ float g_out1[(size_t)NMAX * BB];                  // conv1 out fp32
__device__ __align__(16) unsigned short g_feat16[(size_t)NMAX * AA]; // raw
__device__ __align__(16) unsigned short g_a16[(size_t)NMAX * AA];    // bnrelu1
__device__ __align__(16) unsigned short g_m16[(size_t)NMAX * BB];    // bnrelu2
__device__ __align__(16) unsigned short g_zero[64];          // zero page
__device__ int   g_gidx[KK * NMAX];                          // gather idx / -1
__device__ int   g_mask_u8;
__device__ float g_ps[PB * BB], g_pq[PB * BB];
__device__ float g_s1[AA], g_b1[AA], g_s2[BB], g_b2[BB];
// fp16 weight planes, DENSE: per (k,chunk) plane = 2048 u32, n*16 + pslot(p)
__device__ __align__(16) uint32_t g_W1p[KK * 2 * 2048];
__device__ __align__(16) uint32_t g_W2p[KK * 4 * 2048];
__device__ __align__(16) uint32_t g_Wnp[2 * 2048];

// pair p (0..15) -> interleaved slot so B fragment LDS.64 pairs are adjacent
__host__ __device__ __forceinline__ int pslot(int p) {
    return (p >> 3) * 8 + ((p & 3) * 2) + ((p & 7) >> 2);
}

// pack two fp32 -> f16x2 (low half = first arg)
__device__ __forceinline__ uint32_t cvt2(float lo, float hi) {
    uint32_t r;
    asm("cvt.rn.f16x2.f32 %0, %1, %2;" : "=r"(r) : "f"(hi), "f"(lo));
    return r;
}

// mma.sync m16n8k16 f16 (row.col, fp32 accum)
__device__ __forceinline__ void mma_f16(float* d, uint32_t a0, uint32_t a1,
                                        uint32_t a2, uint32_t a3, uint2 b) {
    asm volatile(
        "mma.sync.aligned.m16n8k16.row.col.f32.f16.f16.f32 "
        "{%0,%1,%2,%3}, {%4,%5,%6,%7}, {%8,%9}, {%0,%1,%2,%3};"
        : "+f"(d[0]), "+f"(d[1]), "+f"(d[2]), "+f"(d[3])
        : "r"(a0), "r"(a1), "r"(a2), "r"(a3), "r"(b.x), "r"(b.y));
}

__device__ __forceinline__ uint32_t smem_u32(const void* p) {
    uint32_t a;
    asm("{ .reg .u64 t; cvta.to.shared.u64 t, %1; cvt.u32.u64 %0, t; }"
        : "=r"(a) : "l"(p));
    return a;
}
__device__ __forceinline__ void cp16(uint32_t dst, const void* src) {
    asm volatile("cp.async.cg.shared.global [%0], [%1], 16;"
                 :: "r"(dst), "l"(src) : "memory");
}
#define CP_COMMIT() asm volatile("cp.async.commit_group;" ::: "memory")
#define CP_WAIT1()  asm volatile("cp.async.wait_group 1;" ::: "memory")

// ---------------- small kernels --------------------------------------------
__global__ void k_detect(const unsigned char* __restrict__ m8) {
    int t = threadIdx.x;
    int ok = (m8[t * KK + KK / 2] != 0) ? 1 : 0;
    int all = __syncthreads_and(ok);
    if (t == 0) g_mask_u8 = all;
}

__global__ void k_gidx(const int* __restrict__ nbr,
                       const void* __restrict__ mp, int N) {
    int i = blockIdx.x * blockDim.x + threadIdx.x;
    if (i >= N) return;
    const bool u8 = (g_mask_u8 != 0);
    const unsigned char* m8  = (const unsigned char*)mp;
    const int*           m32 = (const int*)mp;
#pragma unroll
    for (int k = 0; k < KK; k++) {
        bool m = u8 ? (m8[(size_t)i * KK + k] != 0)
                    : (m32[(size_t)i * KK + k] != 0);
        g_gidx[k * N + i] = m ? nbr[(size_t)i * KK + k] : -1;
    }
}

// feat fp32 -> fp16 raw (for NiN)
__global__ void k_prep(const float* __restrict__ f, int n4) {
    int i = blockIdx.x * blockDim.x + threadIdx.x;
    if (i >= n4) return;
    float4 v = ((const float4*)f)[i];
    uint2 o;
    o.x = cvt2(v.x, v.y);
    o.y = cvt2(v.z, v.w);
    ((uint2*)g_feat16)[i] = o;
}

// bnrelu applied to fp32 src -> fp16 dst
template <int CH>
__global__ void k_bnapply(const float* __restrict__ x,
                          unsigned short* __restrict__ o,
                          const float* __restrict__ scl,
                          const float* __restrict__ bia, int n4) {
    int i = blockIdx.x * blockDim.x + threadIdx.x;
    if (i >= n4) return;
    float4 v = ((const float4*)x)[i];
    int c = (i * 4) & (CH - 1);
    v.x = fmaxf(fmaf(v.x, scl[c],     bia[c]),     0.f);
    v.y = fmaxf(fmaf(v.y, scl[c + 1], bia[c + 1]), 0.f);
    v.z = fmaxf(fmaf(v.z, scl[c + 2], bia[c + 2]), 0.f);
    v.w = fmaxf(fmaf(v.w, scl[c + 3], bia[c + 3]), 0.f);
    uint2 r;
    r.x = cvt2(v.x, v.y);
    r.y = cvt2(v.z, v.w);
    ((uint2*)o)[i] = r;
}

template <int CH, int RG>
__global__ void k_stats(const float* __restrict__ x, int N) {
    int c = threadIdx.x, r = threadIdx.y;
    float s = 0.f, q = 0.f;
    for (int i = blockIdx.x * RG + r; i < N; i += gridDim.x * RG) {
        float v = x[(size_t)i * CH + c];
        s += v; q += v * v;
    }
    __shared__ float sh[RG][CH];
    __shared__ float shq[RG][CH];
    sh[r][c] = s; shq[r][c] = q;
    __syncthreads();
    if (r == 0) {
#pragma unroll
        for (int j = 1; j < RG; j++) { s += sh[j][c]; q += shq[j][c]; }
        g_ps[blockIdx.x * CH + c] = s;
        g_pq[blockIdx.x * CH + c] = q;
    }
}

template <int CH>
__global__ void k_fin(const float* __restrict__ gamma,
                      const float* __restrict__ beta,
                      float* __restrict__ scl, float* __restrict__ bia, int N) {
    int c = threadIdx.x, r = threadIdx.y;
    float s = 0.f, q = 0.f;
    for (int b = r; b < PB; b += 8) { s += g_ps[b * CH + c]; q += g_pq[b * CH + c]; }
    __shared__ float sh[8][CH];
    __shared__ float shq[8][CH];
    sh[r][c] = s; shq[r][c] = q;
    __syncthreads();
    if (r == 0) {
#pragma unroll
        for (int j = 1; j < 8; j++) { s += sh[j][c]; q += shq[j][c]; }
        float mu  = s / (float)N;
        float var = q / (float)N - mu * mu;
        if (var < 0.f) var = 0.f;
        float rs = rsqrtf(var + 1e-4f);
        float sc = gamma[c] * rs;
        scl[c] = sc;
        bia[c] = beta[c] - mu * sc;
    }
}

// weight pack: transpose-to-[n][k], fp16, pslot layout, DENSE planes (2048 u32)
__global__ void k_wcvt(const float* __restrict__ W1, const float* __restrict__ W2,
                       const float* __restrict__ Wn) {
    const int T1 = KK * 2 * 128 * 16;
    const int T2 = T1 + KK * 4 * 128 * 16;
    const int T3 = T2 + 2 * 128 * 16;
    int idx = blockIdx.x * blockDim.x + threadIdx.x;
    if (idx >= T3) return;
    const float* src; uint32_t* dst; int n, p;
    if (idx < T1) {
        int k = idx / (2 * 128 * 16), r = idx % (2 * 128 * 16);
        int ch = r / (128 * 16), r2 = r % (128 * 16);
        n = r2 / 16; p = r2 % 16;
        src = W1 + (size_t)k * 64 * 128 + (size_t)(ch * 32 + 2 * p) * 128 + n;
        dst = g_W1p + (size_t)(k * 2 + ch) * 2048;
    } else if (idx < T2) {
        int i2 = idx - T1;
        int k = i2 / (4 * 128 * 16), r = i2 % (4 * 128 * 16);
        int ch = r / (128 * 16), r2 = r % (128 * 16);
        n = r2 / 16; p = r2 % 16;
        src = W2 + (size_t)k * 128 * 128 + (size_t)(ch * 32 + 2 * p) * 128 + n;
        dst = g_W2p + (size_t)(k * 4 + ch) * 2048;
    } else {
        int i2 = idx - T2;
        int ch = i2 / (128 * 16), r2 = i2 % (128 * 16);
        n = r2 / 16; p = r2 % 16;
        src = Wn + (size_t)(ch * 32 + 2 * p) * 128 + n;
        dst = g_Wnp + (size_t)ch * 2048;
    }
    float w0 = src[0], w1 = src[128];
    __half h0 = __float2half(w0);
    __half h1 = __float2half(w1);
    uint32_t hp = ((uint32_t)*(unsigned short*)&h1 << 16) |
                  (uint32_t)*(unsigned short*)&h0;
    dst[n * 16 + pslot(p)] = hp;
}

// ---------------- pure gather-GEMM conv kernel (fat stages) ------------------
// MODE 0: out  = feat16 @ Wnin                (1 stage, dense, store)
// MODE 1: out1 = sum_k a16[gidx_k] @ W1[k]    (27 stages, store fp32)
// MODE 2: out += sum_k m16[gidx_k] @ W2[k]    (27 stages, RMW add)
// Block: 128 sites x 128 cols; 8 warps (4M x 2N); D in fp32 regs.
// Per stage: A (128 x CIN fp16, gathered rows; masked -> zero page) and
// B (CIN x 128 fp16 plane) land via cp.async into double-buffered smem with
// padded rows (20 u32) for conflict-free fragment access.
// Smem layout per buffer: [A: NCHP*2560 u32][B: NCHP*2560 u32].

template <int CIN, int MODE>
__global__ void __launch_bounds__(256, (CIN == 64) ? 2 : 1) k_conv(
    const unsigned short* __restrict__ src16, float* __restrict__ outp, int N) {

    constexpr int NCHP   = CIN / 32;            // chunk planes
    constexpr int S      = (MODE == 0) ? 1 : KK;
    constexpr int AU32   = NCHP * 2560;         // A u32 per buffer
    constexpr int ABYTES = AU32 * 4;
    constexpr int BUFSZ  = 2 * ABYTES;          // A + B

    extern __shared__ char sm[];
    const uint32_t smb = smem_u32(sm);

    const uint32_t* Wb = (MODE == 0) ? g_Wnp : (MODE == 1 ? g_W1p : g_W2p);

    const int tid = threadIdx.x;
    const int wid = tid >> 5, lane = tid & 31;
    const int qr = lane >> 2, qc = lane & 3;
    const int wm = wid >> 1, wn = wid & 1;
    const int tile = blockIdx.x * 128;
    const int r = tid >> 1, h = tid & 1;
    const int site = tile + r;

    float acc[2][8][4];
#pragma unroll
    for (int a = 0; a < 2; a++)
#pragma unroll
        for (int b = 0; b < 8; b++)
#pragma unroll
            for (int c = 0; c < 4; c++) acc[a][b][c] = 0.f;

    auto rowOf = [&](int s) -> int {
        if (site >= N) return -1;
        if (MODE == 0) return site;
        return g_gidx[(size_t)s * N + site];
    };

    // issue all cp.asyncs for stage s into buffer `buf`
    auto issueStage = [&](int s, int sr, int buf) {
        const uint32_t aB = smb + (uint32_t)buf * BUFSZ;
        const uint32_t bB = aB + ABYTES;
        const char* arow = (const char*)(src16 + (size_t)sr * CIN);
#pragma unroll
        for (int j = 0; j < 2 * NCHP; j++) {
            const int cb = h * (CIN / 2) + j * 8;      // channel base of chunk
            const void* sp = (sr >= 0) ? (const void*)(arow + cb * 2)
                                       : (const void*)g_zero;
            const int cp = cb >> 5, p0 = (cb & 31) >> 1;
            cp16(aB + (uint32_t)(cp * 2560 + r * 20 + p0) * 4, sp);
        }
        const char* bsrc = (const char*)(Wb + (size_t)s * (NCHP * 2048));
#pragma unroll
        for (int j = 0; j < 2 * NCHP; j++) {
            const int c  = tid + j * 256;
            const int pl = c >> 9, cw = c & 511;
            const int n  = cw >> 2, grp = c & 3;
            cp16(bB + (uint32_t)(pl * 2560 + n * 20 + grp * 4) * 4,
                 bsrc + (size_t)c * 16);
        }
    };

    // ---- prologue: stages 0 and 1 in flight
    issueStage(0, rowOf(0), 0);
    CP_COMMIT();
    if (S > 1) issueStage(1, rowOf(1), 1);
    CP_COMMIT();
    int srP = (S > 2) ? rowOf(2) : -1;

    for (int s = 0; s < S; s++) {
        CP_WAIT1();                    // stage s landed (s+1 may still fly)
        __syncthreads();

        const int buf = s & 1;
        const uint32_t* Ab = (const uint32_t*)(sm + buf * BUFSZ);
        const uint32_t* Bb = (const uint32_t*)(sm + buf * BUFSZ + ABYTES);

        // ---- MMA: NCHP chunk planes x 2 k16 steps x (2M x 8N tiles)
#pragma unroll
        for (int cp = 0; cp < NCHP; cp++) {
            const uint32_t* Ap = Ab + cp * 2560;
            const uint32_t* Bp = Bb + cp * 2560;
#pragma unroll
            for (int g = 0; g < 2; g++) {
                uint32_t aq[2][4];
#pragma unroll
                for (int mt = 0; mt < 2; mt++) {
                    const int r0 = wm * 32 + mt * 16 + qr;
                    const int ba = r0 * 20 + g * 8 + qc;
                    aq[mt][0] = Ap[ba];
                    aq[mt][1] = Ap[ba + 160];          // row +8
                    aq[mt][2] = Ap[ba + 4];            // pair qc+4
                    aq[mt][3] = Ap[ba + 164];
                }
#pragma unroll
                for (int nt = 0; nt < 8; nt++) {
                    const int c0b = wn * 64 + nt * 8 + qr;
                    uint2 bf = *(const uint2*)&Bp[c0b * 20 + g * 8 + qc * 2];
                    mma_f16(acc[0][nt], aq[0][0], aq[0][1], aq[0][2], aq[0][3], bf);
                    mma_f16(acc[1][nt], aq[1][0], aq[1][1], aq[1][2], aq[1][3], bf);
                }
            }
        }
        __syncthreads();               // MMA(s) done before refilling buf

        if (s + 2 < S) issueStage(s + 2, srP, buf);
        CP_COMMIT();                   // unconditional (keeps group count)
        if (s + 3 < S) srP = rowOf(s + 3);
    }

    // ---- epilogue: store (MODE 0/1) or RMW add (MODE 2)
#pragma unroll
    for (int mt = 0; mt < 2; mt++) {
        int r0 = wm * 32 + mt * 16 + qr;
        int sA = tile + r0, sB = tile + r0 + 8;
#pragma unroll
        for (int nt = 0; nt < 8; nt++) {
            int col = wn * 64 + nt * 8 + qc * 2;
            if (sA < N) {
                float2* p = (float2*)(outp + (size_t)sA * BB + col);
                if (MODE == 2) {
                    float2 v = *p;
                    v.x += acc[mt][nt][0]; v.y += acc[mt][nt][1];
                    *p = v;
                } else {
                    *p = make_float2(acc[mt][nt][0], acc[mt][nt][1]);
                }
            }
            if (sB < N) {
                float2* p = (float2*)(outp + (size_t)sB * BB + col);
                if (MODE == 2) {
                    float2 v = *p;
                    v.x += acc[mt][nt][2]; v.y += acc[mt][nt][3];
                    *p = v;
                } else {
                    *p = make_float2(acc[mt][nt][2], acc[mt][nt][3]);
                }
            }
        }
    }
}

// ---------------------------------------------------------------------------
extern "C" void kernel_launch(void* const* d_in, const int* in_sizes, int n_in,
                              void* d_out, int out_size) {
    const float* feat   = (const float*)d_in[0];
    const float* gamma1 = (const float*)d_in[1];
    const float* beta1  = (const float*)d_in[2];
    const float* W1     = (const float*)d_in[3];
    const float* gamma2 = (const float*)d_in[4];
    const float* beta2  = (const float*)d_in[5];
    const float* W2     = (const float*)d_in[6];
    const float* Wnin   = (const float*)d_in[7];
    const int*   nbr    = (const int*)d_in[8];
    const void*  mask   = d_in[9];
    float*       out    = (float*)d_out;

    const int N = in_sizes[0] / AA;

    float *p_out1, *p_s1, *p_b1, *p_s2, *p_b2;
    unsigned short *p_f16, *p_a16, *p_m16;
    cudaGetSymbolAddress((void**)&p_out1, g_out1);
    cudaGetSymbolAddress((void**)&p_s1,   g_s1);
    cudaGetSymbolAddress((void**)&p_b1,   g_b1);
    cudaGetSymbolAddress((void**)&p_s2,   g_s2);
    cudaGetSymbolAddress((void**)&p_b2,   g_b2);
    cudaGetSymbolAddress((void**)&p_f16,  g_feat16);
    cudaGetSymbolAddress((void**)&p_a16,  g_a16);
    cudaGetSymbolAddress((void**)&p_m16,  g_m16);

    // dynamic smem opt-in (conv2: 160KB; conv1/NiN: 80KB)
    const int SM64 = 2 * 2 * (2 * 2560 * 4);       // 81920
    const int SM128 = 2 * 2 * (4 * 2560 * 4);      // 163840
    cudaFuncSetAttribute(k_conv<AA, 0>,
                         cudaFuncAttributeMaxDynamicSharedMemorySize, SM64);
    cudaFuncSetAttribute(k_conv<AA, 1>,
                         cudaFuncAttributeMaxDynamicSharedMemorySize, SM64);
    cudaFuncSetAttribute(k_conv<BB, 2>,
                         cudaFuncAttributeMaxDynamicSharedMemorySize, SM128);

    const int gtiles = (N + 127) / 128;
    const int wtot   = KK * 2 * 128 * 16 + KK * 4 * 128 * 16 + 2 * 128 * 16;
    const int n4a    = N * AA / 4;
    const int n4b    = N * BB / 4;

    // prep: mask detect, gather index, raw fp16 feat, weight pack
    k_detect<<<1, 256>>>((const unsigned char*)mask);
    k_gidx<<<(N + 255) / 256, 256>>>(nbr, mask, N);
    k_prep<<<(n4a + 255) / 256, 256>>>(feat, n4a);
    k_wcvt<<<(wtot + 255) / 256, 256>>>(W1, W2, Wnin);

    // BN1 folded affine + apply -> g_a16
    k_stats<AA, 4><<<PB, dim3(AA, 4)>>>(feat, N);
    k_fin<AA><<<1, dim3(AA, 8)>>>(gamma1, beta1, p_s1, p_b1, N);
    k_bnapply<AA><<<(n4a + 255) / 256, 256>>>(feat, p_a16, p_s1, p_b1, n4a);

    // conv1 (27 fat stages) -> g_out1 fp32
    k_conv<AA, 1><<<gtiles, 256, SM64>>>(p_a16, p_out1, N);

    // BN2 folded affine + apply -> g_m16
    k_stats<BB, 2><<<PB, dim3(BB, 2)>>>(p_out1, N);
    k_fin<BB><<<1, dim3(BB, 8)>>>(gamma2, beta2, p_s2, p_b2, N);
    k_bnapply<BB><<<(n4b + 255) / 256, 256>>>(p_out1, p_m16, p_s2, p_b2, n4b);

    // NiN (dense, initializes out), then conv2 RMW-adds
    k_conv<AA, 0><<<gtiles, 256, SM64>>>(p_f16, out, N);
    k_conv<BB, 2><<<gtiles, 256, SM128>>>(p_m16, out, N);
}

// round 12
// speedup vs baseline: 8.1052x; 8.1052x over previous
#include <cuda_runtime.h>
#include <cuda_fp16.h>
#include <cstdint>

// ---------------------------------------------------------------------------
// ResidualBlock: y = feat@Wnin + subconv(bnrelu2(subconv(bnrelu1(feat),W1)),W2)
// N=100000, A=64, B=128, K=27. fp32 in/out.
// Engine: mma.sync m16n8k16 fp16 (HMMA), single pass, fp32 accum.
// Round-12 = round-10 skeleton with:
//   (1) BN hoisted to elementwise prepass (convs are pure gather-GEMMs)
//   (2) triple-buffered smem, ONE barrier per stage
//   (3) NiN fused into conv2 as 2 dense stages (no RMW, one less launch)
// Mask semantics: masked-off rows contribute TRUE zeros.
// ---------------------------------------------------------------------------

#define KK   27
#define AA   64
#define BB   128
#define NMAX 100000
#define PB   512

// ---------------- static device scratch ------------------------------------
__device__ float g_out1[(size_t)NMAX * BB];                  // conv1 out fp32
__device__ __align__(16) unsigned short g_feat16[(size_t)NMAX * AA]; // raw
__device__ __align__(16) unsigned short g_a16[(size_t)NMAX * AA];    // bnrelu1
__device__ __align__(16) unsigned short g_m16[(size_t)NMAX * BB];    // bnrelu2
__device__ int   g_gidx[KK * NMAX];                          // gather idx / -1
__device__ int   g_mask_u8;
__device__ float g_ps[PB * BB], g_pq[PB * BB];
__device__ float g_s1[AA], g_b1[AA], g_s2[BB], g_b2[BB];
// packed fp16 weight planes per (k, chunk): 2560 u32, layout n*20 + pslot(p)
__device__ __align__(16) uint32_t g_W1p[KK * 2 * 2560];
__device__ __align__(16) uint32_t g_W2p[KK * 4 * 2560];
__device__ __align__(16) uint32_t g_Wnp[2 * 2560];

// pair p (0..15) -> interleaved slot so fragment reg pairs are adjacent
__host__ __device__ __forceinline__ int pslot(int p) {
    return (p >> 3) * 8 + ((p & 3) * 2) + ((p & 7) >> 2);
}

// pack two fp32 -> f16x2 (low half = first arg)
__device__ __forceinline__ uint32_t cvt2(float lo, float hi) {
    uint32_t r;
    asm("cvt.rn.f16x2.f32 %0, %1, %2;" : "=r"(r) : "f"(hi), "f"(lo));
    return r;
}

// mma.sync m16n8k16 f16: a={a0.x,a1.x,a0.y,a1.y}, b={b.x,b.y}, d += a@b
__device__ __forceinline__ void mma_f16(float* d, uint2 a0, uint2 a1, uint2 b) {
    asm volatile(
        "mma.sync.aligned.m16n8k16.row.col.f32.f16.f16.f32 "
        "{%0,%1,%2,%3}, {%4,%5,%6,%7}, {%8,%9}, {%0,%1,%2,%3};"
        : "+f"(d[0]), "+f"(d[1]), "+f"(d[2]), "+f"(d[3])
        : "r"(a0.x), "r"(a1.x), "r"(a0.y), "r"(a1.y), "r"(b.x), "r"(b.y));
}

// ---------------- small kernels --------------------------------------------
__global__ void k_detect(const unsigned char* __restrict__ m8) {
    int t = threadIdx.x;
    int ok = (m8[t * KK + KK / 2] != 0) ? 1 : 0;
    int all = __syncthreads_and(ok);
    if (t == 0) g_mask_u8 = all;
}

__global__ void k_gidx(const int* __restrict__ nbr,
                       const void* __restrict__ mp, int N) {
    int i = blockIdx.x * blockDim.x + threadIdx.x;
    if (i >= N) return;
    const bool u8 = (g_mask_u8 != 0);
    const unsigned char* m8  = (const unsigned char*)mp;
    const int*           m32 = (const int*)mp;
#pragma unroll
    for (int k = 0; k < KK; k++) {
        bool m = u8 ? (m8[(size_t)i * KK + k] != 0)
                    : (m32[(size_t)i * KK + k] != 0);
        g_gidx[k * N + i] = m ? nbr[(size_t)i * KK + k] : -1;
    }
}

// feat fp32 -> fp16 raw (for NiN stages)
__global__ void k_prep(const float* __restrict__ f, int n4) {
    int i = blockIdx.x * blockDim.x + threadIdx.x;
    if (i >= n4) return;
    float4 v = ((const float4*)f)[i];
    uint2 o;
    o.x = cvt2(v.x, v.y);
    o.y = cvt2(v.z, v.w);
    ((uint2*)g_feat16)[i] = o;
}

// bnrelu applied to fp32 src -> fp16 dst (hoisted BN)
template <int CH>
__global__ void k_bnapply(const float* __restrict__ x,
                          unsigned short* __restrict__ o,
                          const float* __restrict__ scl,
                          const float* __restrict__ bia, int n4) {
    int i = blockIdx.x * blockDim.x + threadIdx.x;
    if (i >= n4) return;
    float4 v = ((const float4*)x)[i];
    int c = (i * 4) & (CH - 1);
    v.x = fmaxf(fmaf(v.x, scl[c],     bia[c]),     0.f);
    v.y = fmaxf(fmaf(v.y, scl[c + 1], bia[c + 1]), 0.f);
    v.z = fmaxf(fmaf(v.z, scl[c + 2], bia[c + 2]), 0.f);
    v.w = fmaxf(fmaf(v.w, scl[c + 3], bia[c + 3]), 0.f);
    uint2 r;
    r.x = cvt2(v.x, v.y);
    r.y = cvt2(v.z, v.w);
    ((uint2*)o)[i] = r;
}

template <int CH, int RG>
__global__ void k_stats(const float* __restrict__ x, int N) {
    int c = threadIdx.x, r = threadIdx.y;
    float s = 0.f, q = 0.f;
    for (int i = blockIdx.x * RG + r; i < N; i += gridDim.x * RG) {
        float v = x[(size_t)i * CH + c];
        s += v; q += v * v;
    }
    __shared__ float sh[RG][CH];
    __shared__ float shq[RG][CH];
    sh[r][c] = s; shq[r][c] = q;
    __syncthreads();
    if (r == 0) {
#pragma unroll
        for (int j = 1; j < RG; j++) { s += sh[j][c]; q += shq[j][c]; }
        g_ps[blockIdx.x * CH + c] = s;
        g_pq[blockIdx.x * CH + c] = q;
    }
}

template <int CH>
__global__ void k_fin(const float* __restrict__ gamma,
                      const float* __restrict__ beta,
                      float* __restrict__ scl, float* __restrict__ bia, int N) {
    int c = threadIdx.x, r = threadIdx.y;
    float s = 0.f, q = 0.f;
    for (int b = r; b < PB; b += 8) { s += g_ps[b * CH + c]; q += g_pq[b * CH + c]; }
    __shared__ float sh[8][CH];
    __shared__ float shq[8][CH];
    sh[r][c] = s; shq[r][c] = q;
    __syncthreads();
    if (r == 0) {
#pragma unroll
        for (int j = 1; j < 8; j++) { s += sh[j][c]; q += shq[j][c]; }
        float mu  = s / (float)N;
        float var = q / (float)N - mu * mu;
        if (var < 0.f) var = 0.f;
        float rs = rsqrtf(var + 1e-4f);
        float sc = gamma[c] * rs;
        scl[c] = sc;
        bia[c] = beta[c] - mu * sc;
    }
}

// weight pack (round-10 verbatim): transpose-to-[n][k], fp16, pslot layout
__global__ void k_wcvt(const float* __restrict__ W1, const float* __restrict__ W2,
                       const float* __restrict__ Wn) {
    const int T1 = KK * 2 * 128 * 16;
    const int T2 = T1 + KK * 4 * 128 * 16;
    const int T3 = T2 + 2 * 128 * 16;
    int idx = blockIdx.x * blockDim.x + threadIdx.x;
    if (idx >= T3) return;
    const float* src; uint32_t* dst; int n, p;
    if (idx < T1) {
        int k = idx / (2 * 128 * 16), r = idx % (2 * 128 * 16);
        int ch = r / (128 * 16), r2 = r % (128 * 16);
        n = r2 / 16; p = r2 % 16;
        src = W1 + (size_t)k * 64 * 128 + (size_t)(ch * 32 + 2 * p) * 128 + n;
        dst = g_W1p + (size_t)(k * 2 + ch) * 2560;
    } else if (idx < T2) {
        int i2 = idx - T1;
        int k = i2 / (4 * 128 * 16), r = i2 % (4 * 128 * 16);
        int ch = r / (128 * 16), r2 = r % (128 * 16);
        n = r2 / 16; p = r2 % 16;
        src = W2 + (size_t)k * 128 * 128 + (size_t)(ch * 32 + 2 * p) * 128 + n;
        dst = g_W2p + (size_t)(k * 4 + ch) * 2560;
    } else {
        int i2 = idx - T2;
        int ch = i2 / (128 * 16), r2 = i2 % (128 * 16);
        n = r2 / 16; p = r2 % 16;
        src = Wn + (size_t)(ch * 32 + 2 * p) * 128 + n;
        dst = g_Wnp + (size_t)ch * 2560;
    }
    float w0 = src[0], w1 = src[128];
    __half h0 = __float2half(w0);
    __half h1 = __float2half(w1);
    uint32_t hp = ((uint32_t)*(unsigned short*)&h1 << 16) |
                  (uint32_t)*(unsigned short*)&h0;
    dst[n * 20 + pslot(p)] = hp;
}

// ---------------- pure gather-GEMM conv kernel -------------------------------
// MODE 1: out1 = sum_k a16[gidx_k] @ W1[k]                 (54 stages)
// MODE 2: out  = feat16 @ Wnin + sum_k m16[gidx_k] @ W2[k] (2+108 stages)
// Block: 128 sites x 128 cols; 8 warps (4M x 2N); D in fp32 regs, write-once.
// Stage = 32-channel chunk. Triple-buffered smem (one barrier per stage):
//   iter s: MMA(s, buf s%3) -> STS(s+1, buf (s+1)%3) -> LDG(s+2) -> bar
// Buffers of MMA(s)/STS(s+1)/last-write(s-2) are distinct mod 3 => race-free.

#define BUFU32 (2560 + 2560)                 // Ah plane + Bs plane (u32)
#define SMEMB  (3 * BUFU32 * 4)              // 61440 bytes

template <int MODE>
__global__ void __launch_bounds__(256, 2) k_conv(
    const unsigned short* __restrict__ src16, float* __restrict__ outp, int N) {

    constexpr int S = (MODE == 1) ? (KK * 2) : (2 + KK * 4);

    extern __shared__ char sm[];

    const int tid = threadIdx.x;
    const int wid = tid >> 5, lane = tid & 31;
    const int qr = lane >> 2, qc = lane & 3;
    const int wm = wid >> 1, wn = wid & 1;
    const int tile = blockIdx.x * 128;
    const int r = tid >> 1, h = tid & 1;
    const int site = tile + r;

    float acc[2][8][4];
#pragma unroll
    for (int a = 0; a < 2; a++)
#pragma unroll
        for (int b = 0; b < 8; b++)
#pragma unroll
            for (int c = 0; c < 4; c++) acc[a][b][c] = 0.f;

    // ---- stage decode ------------------------------------------------------
    auto rowOf = [&](int s) -> int {
        if (site >= N) return -1;
        if (MODE == 2 && s < 2) return site;                 // NiN dense
        int k = (MODE == 1) ? (s >> 1) : ((s - 2) >> 2);
        return g_gidx[(size_t)k * N + site];
    };

    // ---- staged registers (stage data held one stage ahead) ----------------
    uint4 rA2[2];          // 16 fp16 channels for this thread's half-row
    uint4 rB[3];           // weight plane chunk (640 uint4 over 256 threads)
    int   srA;             // row validity of staged stage
    int   srN;             // prefetched row for next stage

    auto ldA = [&](int s, int sr) {
        const unsigned short* sp;
        int stride, c0;
        if (MODE == 2 && s < 2) { sp = g_feat16; stride = AA; c0 = s * 32; }
        else if (MODE == 1)     { sp = src16;    stride = AA; c0 = (s & 1) * 32; }
        else                    { sp = src16;    stride = BB; c0 = ((s - 2) & 3) * 32; }
        const uint4* rp = (const uint4*)(sp + (size_t)sr * stride + c0 + h * 16);
        if (sr >= 0) { rA2[0] = rp[0]; rA2[1] = rp[1]; }
    };
    auto ldB = [&](int s) {
        const uint32_t* bp;
        if (MODE == 1)      bp = g_W1p + (size_t)s * 2560;
        else if (s < 2)     bp = g_Wnp + (size_t)s * 2560;
        else                bp = g_W2p + (size_t)(s - 2) * 2560;
        const uint4* wp = (const uint4*)bp;
#pragma unroll
        for (int j = 0; j < 3; j++) {
            int idx = tid + j * 256;
            if (idx < 640) rB[j] = wp[idx];
        }
    };
    // store staged stage into buffer (pure repack; zeros for invalid rows)
    auto stStage = [&](int buf) {
        uint32_t* Ab = (uint32_t*)(sm + buf * (BUFU32 * 4));
        uint32_t* Bb = Ab + 2560;
        {
            uint4* bd = (uint4*)Bb;
#pragma unroll
            for (int j = 0; j < 3; j++) {
                int idx = tid + j * 256;
                if (idx < 640) bd[idx] = rB[j];
            }
        }
        const int sr = srA;
        const uint32_t* aw = (const uint32_t*)rA2;
        const uint32_t abase = (uint32_t)r * 20u + (uint32_t)h * 8u;
#pragma unroll
        for (int j = 0; j < 4; j++) {
            uint32_t p0 = 0u, p1 = 0u;
            if (sr >= 0) { p0 = aw[2 * j]; p1 = aw[2 * j + 1]; }
            const int s0 = pslot(h * 8 + j * 2) - h * 8;
            const int s1 = pslot(h * 8 + j * 2 + 1) - h * 8;
            Ab[abase + s0] = p0;  Ab[abase + s1] = p1;
        }
    };

    // ---- prologue: stage 0 staged + stored; stage 1 staged ----------------
    srA = rowOf(0);
    ldA(0, srA);
    ldB(0);
    stStage(0);
    srN = (S > 1) ? rowOf(1) : -1;
    if (S > 1) { ldA(1, srN); ldB(1); }
    srA = srN;
    srN = (S > 2) ? rowOf(2) : -1;
    __syncthreads();                    // buffer 0 visible

    // ---- main loop: ONE barrier per stage ---------------------------------
    int bufMMA = 0;
    for (int s = 0; s < S; s++) {
        // MMA(s) from buf[s%3]
        const uint32_t* Ab = (const uint32_t*)(sm + bufMMA * (BUFU32 * 4));
        const uint32_t* Bb = Ab + 2560;
#pragma unroll
        for (int g = 0; g < 2; g++) {
            uint2 a0[2], a1[2];
#pragma unroll
            for (int mt = 0; mt < 2; mt++) {
                int r0 = wm * 32 + mt * 16 + qr;
                a0[mt] = *(const uint2*)&Ab[r0 * 20 + g * 8 + qc * 2];
                a1[mt] = *(const uint2*)&Ab[(r0 + 8) * 20 + g * 8 + qc * 2];
            }
#pragma unroll
            for (int nt = 0; nt < 8; nt++) {
                int c0b = wn * 64 + nt * 8 + qr;
                uint2 bf = *(const uint2*)&Bb[c0b * 20 + g * 8 + qc * 2];
                mma_f16(acc[0][nt], a0[0], a1[0], bf);
                mma_f16(acc[1][nt], a0[1], a1[1], bf);
            }
        }

        // STS(s+1) into buf[(s+1)%3]
        int bufN = bufMMA + 1; if (bufN == 3) bufN = 0;
        if (s + 1 < S) stStage(bufN);

        // LDG(s+2) into staged regs (cover = next stage's MMA)
        if (s + 2 < S) {
            ldA(s + 2, srN);
            ldB(s + 2);
            srA = srN;
            if (s + 3 < S) srN = rowOf(s + 3);
        }

        __syncthreads();
        bufMMA = bufN;
    }

    // ---- epilogue: write-once dense output --------------------------------
#pragma unroll
    for (int mt = 0; mt < 2; mt++) {
        int r0 = wm * 32 + mt * 16 + qr;
        int sA = tile + r0, sB = tile + r0 + 8;
#pragma unroll
        for (int nt = 0; nt < 8; nt++) {
            int col = wn * 64 + nt * 8 + qc * 2;
            if (sA < N)
                *(float2*)(outp + (size_t)sA * BB + col) =
                    make_float2(acc[mt][nt][0], acc[mt][nt][1]);
            if (sB < N)
                *(float2*)(outp + (size_t)sB * BB + col) =
                    make_float2(acc[mt][nt][2], acc[mt][nt][3]);
        }
    }
}

// ---------------------------------------------------------------------------
extern "C" void kernel_launch(void* const* d_in, const int* in_sizes, int n_in,
                              void* d_out, int out_size) {
    const float* feat   = (const float*)d_in[0];
    const float* gamma1 = (const float*)d_in[1];
    const float* beta1  = (const float*)d_in[2];
    const float* W1     = (const float*)d_in[3];
    const float* gamma2 = (const float*)d_in[4];
    const float* beta2  = (const float*)d_in[5];
    const float* W2     = (const float*)d_in[6];
    const float* Wnin   = (const float*)d_in[7];
    const int*   nbr    = (const int*)d_in[8];
    const void*  mask   = d_in[9];
    float*       out    = (float*)d_out;

    const int N = in_sizes[0] / AA;

    float *p_out1, *p_s1, *p_b1, *p_s2, *p_b2;
    unsigned short *p_a16, *p_m16;
    cudaGetSymbolAddress((void**)&p_out1, g_out1);
    cudaGetSymbolAddress((void**)&p_s1,   g_s1);
    cudaGetSymbolAddress((void**)&p_b1,   g_b1);
    cudaGetSymbolAddress((void**)&p_s2,   g_s2);
    cudaGetSymbolAddress((void**)&p_b2,   g_b2);
    cudaGetSymbolAddress((void**)&p_a16,  g_a16);
    cudaGetSymbolAddress((void**)&p_m16,  g_m16);

    cudaFuncSetAttribute(k_conv<1>,
                         cudaFuncAttributeMaxDynamicSharedMemorySize, SMEMB);
    cudaFuncSetAttribute(k_conv<2>,
                         cudaFuncAttributeMaxDynamicSharedMemorySize, SMEMB);

    const int gtiles = (N + 127) / 128;
    const int wtot   = KK * 2 * 128 * 16 + KK * 4 * 128 * 16 + 2 * 128 * 16;
    const int n4a    = N * AA / 4;
    const int n4b    = N * BB / 4;

    // prep: mask detect, gather index, raw fp16 feat, weight pack
    k_detect<<<1, 256>>>((const unsigned char*)mask);
    k_gidx<<<(N + 255) / 256, 256>>>(nbr, mask, N);
    k_prep<<<(n4a + 255) / 256, 256>>>(feat, n4a);
    k_wcvt<<<(wtot + 255) / 256, 256>>>(W1, W2, Wnin);

    // BN1 folded affine + apply -> g_a16
    k_stats<AA, 4><<<PB, dim3(AA, 4)>>>(feat, N);
    k_fin<AA><<<1, dim3(AA, 8)>>>(gamma1, beta1, p_s1, p_b1, N);
    k_bnapply<AA><<<(n4a + 255) / 256, 256>>>(feat, p_a16, p_s1, p_b1, n4a);

    // conv1 -> g_out1 fp32
    k_conv<1><<<gtiles, 256, SMEMB>>>(p_a16, p_out1, N);

    // BN2 folded affine + apply -> g_m16
    k_stats<BB, 2><<<PB, dim3(BB, 2)>>>(p_out1, N);
    k_fin<BB><<<1, dim3(BB, 8)>>>(gamma2, beta2, p_s2, p_b2, N);
    k_bnapply<BB><<<(n4b + 255) / 256, 256>>>(p_out1, p_m16, p_s2, p_b2, n4b);

    // conv2 (NiN fused as 2 leading dense stages) -> out (write-once)
    k_conv<2><<<gtiles, 256, SMEMB>>>(p_m16, out, N);
}

// round 13
// speedup vs baseline: 8.6643x; 1.0690x over previous
#include <cuda_runtime.h>
#include <cuda_fp16.h>
#include <cstdint>

// ---------------------------------------------------------------------------
// ResidualBlock: y = feat@Wnin + subconv(bnrelu2(subconv(bnrelu1(feat),W1)),W2)
// N=100000, A=64, B=128, K=27. fp32 in/out.
// Engine: mma.sync m16n8k16 fp16 (HMMA), single pass, fp32 accum.
// Round-13: activation buffers stored PRE-PERMUTED in fragment-slot order
// (A-fill = pure uint4 copy), conv1 outputs fp16 directly (no fp32 mid),
// NiN weights concatenated (linear B walk), fused prep kernels.
// Mask semantics: masked-off rows contribute TRUE zeros.
// ---------------------------------------------------------------------------

#define KK   27
#define AA   64
#define BB   128
#define NMAX 100000
#define PB   512

// ---------------- static device scratch ------------------------------------
// fp16 activation buffers as u32 (=channel-pair) arrays, fragment-slot order
__device__ __align__(16) uint32_t g_f16[(size_t)NMAX * 32];   // raw feat
__device__ __align__(16) uint32_t g_a16[(size_t)NMAX * 32];   // bnrelu1(feat)
__device__ __align__(16) uint32_t g_mraw[(size_t)NMAX * 64];  // conv1 out
__device__ __align__(16) uint32_t g_m16[(size_t)NMAX * 64];   // bnrelu2(mid)
__device__ int   g_gidx[KK * NMAX];                           // gather idx/-1
__device__ float g_ps[PB * BB], g_pq[PB * BB];
__device__ float g_s1[AA], g_b1[AA], g_s2[BB], g_b2[BB];
// packed fp16 weight planes (2560 u32 each, n*20 + pslot(p)); stage-linear
__device__ __align__(16) uint32_t g_W1p[KK * 2 * 2560];
__device__ __align__(16) uint32_t g_Wcat[(2 + KK * 4) * 2560]; // [Wnin|W2]

// pair p (0..15) -> interleaved slot so fragment reg pairs are adjacent
__host__ __device__ __forceinline__ int pslot(int p) {
    return (p >> 3) * 8 + ((p & 3) * 2) + ((p & 7) >> 2);
}
// inverse of pslot
__host__ __device__ __forceinline__ int ipslot(int q) {
    int qq = q & 7, base = q & 8;
    return base + ((qq & 1) ? 4 + (qq >> 1) : (qq >> 1));
}

// pack two fp32 -> f16x2 (low half = first arg)
__device__ __forceinline__ uint32_t cvt2(float lo, float hi) {
    uint32_t r;
    asm("cvt.rn.f16x2.f32 %0, %1, %2;" : "=r"(r) : "f"(hi), "f"(lo));
    return r;
}

// mma.sync m16n8k16 f16: a={a0.x,a1.x,a0.y,a1.y}, b={b.x,b.y}, d += a@b
__device__ __forceinline__ void mma_f16(float* d, uint2 a0, uint2 a1, uint2 b) {
    asm volatile(
        "mma.sync.aligned.m16n8k16.row.col.f32.f16.f16.f32 "
        "{%0,%1,%2,%3}, {%4,%5,%6,%7}, {%8,%9}, {%0,%1,%2,%3};"
        : "+f"(d[0]), "+f"(d[1]), "+f"(d[2]), "+f"(d[3])
        : "r"(a0.x), "r"(a1.x), "r"(a0.y), "r"(a1.y), "r"(b.x), "r"(b.y));
}

// ---------------- small kernels --------------------------------------------
// gather index precompute with per-block mask-dtype detection
__global__ void k_gidx(const int* __restrict__ nbr,
                       const void* __restrict__ mp, int N) {
    __shared__ int s_u8;
    int t = threadIdx.x;
    int i = blockIdx.x * 256 + t;
    int probe = (i < N) ? i : (N - 1);
    int ok = (((const unsigned char*)mp)[(size_t)probe * KK + KK / 2] != 0);
    int all = __syncthreads_and(ok);
    if (t == 0) s_u8 = all;
    __syncthreads();
    if (i >= N) return;
    const bool u8 = (s_u8 != 0);
    const unsigned char* m8  = (const unsigned char*)mp;
    const int*           m32 = (const int*)mp;
#pragma unroll
    for (int k = 0; k < KK; k++) {
        bool m = u8 ? (m8[(size_t)i * KK + k] != 0)
                    : (m32[(size_t)i * KK + k] != 0);
        g_gidx[k * N + i] = m ? nbr[(size_t)i * KK + k] : -1;
    }
}

// BN1 apply + raw convert, fused: feat fp32 -> g_a16 (bn) + g_f16 (raw),
// both fp16 PERMUTED (pair p at pslot(p) within each 16-u32 chunk).
__global__ void k_bn1(const float* __restrict__ x,
                      const float* __restrict__ scl,
                      const float* __restrict__ bia, int n16) {
    int i = blockIdx.x * blockDim.x + threadIdx.x;
    if (i >= n16) return;                 // i indexes float4 over N*16
    float4 v = ((const float4*)x)[i];
    int row = i >> 4, t = i & 15;
    int c = t * 4;                        // true channel base
    int cc = t >> 3, p0 = (2 * t) & 15;
    int base = row * 32 + cc * 16;
    int pos0 = base + pslot(p0), pos1 = base + pslot(p0 + 1);
    g_f16[pos0] = cvt2(v.x, v.y);
    g_f16[pos1] = cvt2(v.z, v.w);
    float4 w;
    w.x = fmaxf(fmaf(v.x, scl[c],     bia[c]),     0.f);
    w.y = fmaxf(fmaf(v.y, scl[c + 1], bia[c + 1]), 0.f);
    w.z = fmaxf(fmaf(v.z, scl[c + 2], bia[c + 2]), 0.f);
    w.w = fmaxf(fmaf(v.w, scl[c + 3], bia[c + 3]), 0.f);
    g_a16[pos0] = cvt2(w.x, w.y);
    g_a16[pos1] = cvt2(w.z, w.w);
}

// BN2 apply: g_mraw (fp16 permuted) -> g_m16; positions identity, scale
// arrays are STORAGE-indexed (fin2 does the gamma/beta index mapping).
__global__ void k_bn2(const float* __restrict__ scl,
                      const float* __restrict__ bia, int n32) {
    int i = blockIdx.x * blockDim.x + threadIdx.x;
    if (i >= n32) return;                 // i indexes uint2 over N*32
    uint2 x = ((const uint2*)g_mraw)[i];
    int c = (i & 31) * 4;                 // storage channel base
    float2 f0 = __half22float2(*(const __half2*)&x.x);
    float2 f1 = __half22float2(*(const __half2*)&x.y);
    f0.x = fmaxf(fmaf(f0.x, scl[c],     bia[c]),     0.f);
    f0.y = fmaxf(fmaf(f0.y, scl[c + 1], bia[c + 1]), 0.f);
    f1.x = fmaxf(fmaf(f1.x, scl[c + 2], bia[c + 2]), 0.f);
    f1.y = fmaxf(fmaf(f1.y, scl[c + 3], bia[c + 3]), 0.f);
    uint2 r;
    r.x = cvt2(f0.x, f0.y);
    r.y = cvt2(f1.x, f1.y);
    ((uint2*)g_m16)[i] = r;
}

// fp32 stats (BN1): block (CH, RG)
template <int CH, int RG>
__global__ void k_stats(const float* __restrict__ x, int N) {
    int c = threadIdx.x, r = threadIdx.y;
    float s = 0.f, q = 0.f;
    for (int i = blockIdx.x * RG + r; i < N; i += gridDim.x * RG) {
        float v = x[(size_t)i * CH + c];
        s += v; q += v * v;
    }
    __shared__ float sh[RG][CH];
    __shared__ float shq[RG][CH];
    sh[r][c] = s; shq[r][c] = q;
    __syncthreads();
    if (r == 0) {
#pragma unroll
        for (int j = 1; j < RG; j++) { s += sh[j][c]; q += shq[j][c]; }
        g_ps[blockIdx.x * CH + c] = s;
        g_pq[blockIdx.x * CH + c] = q;
    }
}

// fp16 stats (BN2) over g_mraw: block (64 positions, RG); 2 channels/thread
template <int RG>
__global__ void k_stats16(int N) {
    int pos = threadIdx.x, r = threadIdx.y;
    float sl = 0.f, ql = 0.f, sh2 = 0.f, qh = 0.f;
    for (int i = blockIdx.x * RG + r; i < N; i += gridDim.x * RG) {
        uint32_t w = g_mraw[(size_t)i * 64 + pos];
        float2 f = __half22float2(*(const __half2*)&w);
        sl += f.x; ql += f.x * f.x;
        sh2 += f.y; qh += f.y * f.y;
    }
    __shared__ float sa[RG][128];
    __shared__ float sb[RG][128];
    sa[r][pos * 2] = sl;  sa[r][pos * 2 + 1] = sh2;
    sb[r][pos * 2] = ql;  sb[r][pos * 2 + 1] = qh;
    __syncthreads();
    if (r == 0) {
        float s0 = sa[0][pos * 2], s1 = sa[0][pos * 2 + 1];
        float q0 = sb[0][pos * 2], q1 = sb[0][pos * 2 + 1];
#pragma unroll
        for (int j = 1; j < RG; j++) {
            s0 += sa[j][pos * 2]; s1 += sa[j][pos * 2 + 1];
            q0 += sb[j][pos * 2]; q1 += sb[j][pos * 2 + 1];
        }
        g_ps[blockIdx.x * 128 + pos * 2]     = s0;
        g_ps[blockIdx.x * 128 + pos * 2 + 1] = s1;
        g_pq[blockIdx.x * 128 + pos * 2]     = q0;
        g_pq[blockIdx.x * 128 + pos * 2 + 1] = q1;
    }
}

// finisher: MAP=true translates storage channel -> true channel for gamma/beta
template <int CH, bool MAP>
__global__ void k_fin(const float* __restrict__ gamma,
                      const float* __restrict__ beta,
                      float* __restrict__ scl, float* __restrict__ bia, int N) {
    int c = threadIdx.x, r = threadIdx.y;
    float s = 0.f, q = 0.f;
    for (int b = r; b < PB; b += 8) { s += g_ps[b * CH + c]; q += g_pq[b * CH + c]; }
    __shared__ float sh[8][CH];
    __shared__ float shq[8][CH];
    sh[r][c] = s; shq[r][c] = q;
    __syncthreads();
    if (r == 0) {
#pragma unroll
        for (int j = 1; j < 8; j++) { s += sh[j][c]; q += shq[j][c]; }
        float mu  = s / (float)N;
        float var = q / (float)N - mu * mu;
        if (var < 0.f) var = 0.f;
        float rs = rsqrtf(var + 1e-4f);
        int tc = c;
        if (MAP) {
            int cc = c >> 5, wi = c & 31, qn = wi >> 1, e = wi & 1;
            tc = cc * 32 + ipslot(qn) * 2 + e;
        }
        float sc = gamma[tc] * rs;
        scl[c] = sc;
        bia[c] = beta[tc] - mu * sc;
    }
}

// weight pack: transpose-to-[n][k], fp16, pslot layout, stage-linear planes
__global__ void k_wcvt(const float* __restrict__ W1, const float* __restrict__ W2,
                       const float* __restrict__ Wn) {
    const int T1 = KK * 2 * 128 * 16;
    const int T2 = T1 + KK * 4 * 128 * 16;
    const int T3 = T2 + 2 * 128 * 16;
    int idx = blockIdx.x * blockDim.x + threadIdx.x;
    if (idx >= T3) return;
    const float* src; uint32_t* dst; int n, p;
    if (idx < T1) {
        int k = idx / (2 * 128 * 16), r = idx % (2 * 128 * 16);
        int ch = r / (128 * 16), r2 = r % (128 * 16);
        n = r2 / 16; p = r2 % 16;
        src = W1 + (size_t)k * 64 * 128 + (size_t)(ch * 32 + 2 * p) * 128 + n;
        dst = g_W1p + (size_t)(k * 2 + ch) * 2560;
    } else if (idx < T2) {
        int i2 = idx - T1;
        int k = i2 / (4 * 128 * 16), r = i2 % (4 * 128 * 16);
        int ch = r / (128 * 16), r2 = r % (128 * 16);
        n = r2 / 16; p = r2 % 16;
        src = W2 + (size_t)k * 128 * 128 + (size_t)(ch * 32 + 2 * p) * 128 + n;
        dst = g_Wcat + (size_t)(2 + k * 4 + ch) * 2560;
    } else {
        int i2 = idx - T2;
        int ch = i2 / (128 * 16), r2 = i2 % (128 * 16);
        n = r2 / 16; p = r2 % 16;
        src = Wn + (size_t)(ch * 32 + 2 * p) * 128 + n;
        dst = g_Wcat + (size_t)ch * 2560;
    }
    float w0 = src[0], w1 = src[128];
    __half h0 = __float2half(w0);
    __half h1 = __float2half(w1);
    uint32_t hp = ((uint32_t)*(unsigned short*)&h1 << 16) |
                  (uint32_t)*(unsigned short*)&h0;
    dst[n * 20 + pslot(p)] = hp;
}

// ---------------- pure gather-GEMM conv kernel -------------------------------
// MODE 1: mraw = sum_k a16[gidx_k] @ W1[k]                 (54 stages, fp16)
// MODE 2: out  = f16 @ Wnin + sum_k m16[gidx_k] @ W2[k]    (110 st, fp32)
// Block: 128 sites x 128 cols; 8 warps (4M x 2N); D in fp32 regs, write-once.
// Sources pre-permuted -> A-fill is a pure uint4 copy (2 LDG.128 + 2 STS.128).
// Triple-buffered smem, one barrier per stage.

#define BUFU32 (2560 + 2560)
#define SMEMB  (3 * BUFU32 * 4)

template <int MODE>
__global__ void __launch_bounds__(256, 2) k_conv(
    const uint32_t* __restrict__ src32, uint32_t* __restrict__ mid32,
    float* __restrict__ outp, int N) {

    constexpr int S = (MODE == 1) ? (KK * 2) : (2 + KK * 4);

    extern __shared__ char sm[];

    const int tid = threadIdx.x;
    const int wid = tid >> 5, lane = tid & 31;
    const int qr = lane >> 2, qc = lane & 3;
    const int wm = wid >> 1, wn = wid & 1;
    const int tile = blockIdx.x * 128;
    const int r = tid >> 1, h = tid & 1;
    const int site = tile + r;

    float acc[2][8][4];
#pragma unroll
    for (int a = 0; a < 2; a++)
#pragma unroll
        for (int b = 0; b < 8; b++)
#pragma unroll
            for (int c = 0; c < 4; c++) acc[a][b][c] = 0.f;

    auto rowOf = [&](int s) -> int {
        if (site >= N) return -1;
        if (MODE == 2 && s < 2) return site;                 // NiN dense
        int k = (MODE == 1) ? (s >> 1) : ((s - 2) >> 2);
        return g_gidx[(size_t)k * N + site];
    };

    uint4 rA2[2];
    uint4 rB[3];
    int   srA, srN;

    auto ldA = [&](int s, int sr) {
        const uint32_t* sp; int stride, c16;
        if (MODE == 2 && s < 2) { sp = g_f16;  stride = 32; c16 = s * 16; }
        else if (MODE == 1)     { sp = src32;  stride = 32; c16 = (s & 1) * 16; }
        else                    { sp = src32;  stride = 64; c16 = ((s - 2) & 3) * 16; }
        const uint4* rp = (const uint4*)(sp + (size_t)sr * stride + c16 + h * 8);
        if (sr >= 0) { rA2[0] = rp[0]; rA2[1] = rp[1]; }
    };
    auto ldB = [&](int s) {
        const uint32_t* bp = (MODE == 1) ? (g_W1p + (size_t)s * 2560)
                                         : (g_Wcat + (size_t)s * 2560);
        const uint4* wp = (const uint4*)bp;
#pragma unroll
        for (int j = 0; j < 3; j++) {
            int idx = tid + j * 256;
            if (idx < 640) rB[j] = wp[idx];
        }
    };
    auto stStage = [&](int buf) {
        uint32_t* Ab = (uint32_t*)(sm + buf * (BUFU32 * 4));
        uint32_t* Bb = Ab + 2560;
        {
            uint4* bd = (uint4*)Bb;
#pragma unroll
            for (int j = 0; j < 3; j++) {
                int idx = tid + j * 256;
                if (idx < 640) bd[idx] = rB[j];
            }
        }
        uint4* Aq = (uint4*)(Ab + r * 20 + h * 8);
        if (srA >= 0) { Aq[0] = rA2[0]; Aq[1] = rA2[1]; }
        else {
            uint4 z = make_uint4(0u, 0u, 0u, 0u);
            Aq[0] = z; Aq[1] = z;
        }
    };

    // ---- prologue
    srA = rowOf(0);
    ldA(0, srA);
    ldB(0);
    stStage(0);
    srN = (S > 1) ? rowOf(1) : -1;
    if (S > 1) { ldA(1, srN); ldB(1); }
    srA = srN;
    srN = (S > 2) ? rowOf(2) : -1;
    __syncthreads();

    // ---- main loop: one barrier per stage
    int bufMMA = 0;
#pragma unroll 3
    for (int s = 0; s < S; s++) {
        const uint32_t* Ab = (const uint32_t*)(sm + bufMMA * (BUFU32 * 4));
        const uint32_t* Bb = Ab + 2560;
#pragma unroll
        for (int g = 0; g < 2; g++) {
            uint2 a0[2], a1[2];
#pragma unroll
            for (int mt = 0; mt < 2; mt++) {
                int r0 = wm * 32 + mt * 16 + qr;
                a0[mt] = *(const uint2*)&Ab[r0 * 20 + g * 8 + qc * 2];
                a1[mt] = *(const uint2*)&Ab[(r0 + 8) * 20 + g * 8 + qc * 2];
            }
#pragma unroll
            for (int nt = 0; nt < 8; nt++) {
                int c0b = wn * 64 + nt * 8 + qr;
                uint2 bf = *(const uint2*)&Bb[c0b * 20 + g * 8 + qc * 2];
                mma_f16(acc[0][nt], a0[0], a1[0], bf);
                mma_f16(acc[1][nt], a0[1], a1[1], bf);
            }
        }

        int bufN = bufMMA + 1; if (bufN == 3) bufN = 0;
        if (s + 1 < S) stStage(bufN);
        if (s + 2 < S) {
            ldA(s + 2, srN);
            ldB(s + 2);
            srA = srN;
            if (s + 3 < S) srN = rowOf(s + 3);
        }
        __syncthreads();
        bufMMA = bufN;
    }

    // ---- epilogue
#pragma unroll
    for (int mt = 0; mt < 2; mt++) {
        int r0 = wm * 32 + mt * 16 + qr;
        int sA = tile + r0, sB = tile + r0 + 8;
#pragma unroll
        for (int nt = 0; nt < 8; nt++) {
            if (MODE == 1) {
                // fp16 permuted write: pair P at slot pslot(P&15) of chunk P>>4
                int P = wn * 32 + nt * 4 + qc;
                int pos = (P >> 4) * 16 + pslot(P & 15);
                if (sA < N)
                    mid32[(size_t)sA * 64 + pos] =
                        cvt2(acc[mt][nt][0], acc[mt][nt][1]);
                if (sB < N)
                    mid32[(size_t)sB * 64 + pos] =
                        cvt2(acc[mt][nt][2], acc[mt][nt][3]);
            } else {
                int col = wn * 64 + nt * 8 + qc * 2;
                if (sA < N)
                    *(float2*)(outp + (size_t)sA * BB + col) =
                        make_float2(acc[mt][nt][0], acc[mt][nt][1]);
                if (sB < N)
                    *(float2*)(outp + (size_t)sB * BB + col) =
                        make_float2(acc[mt][nt][2], acc[mt][nt][3]);
            }
        }
    }
}

// ---------------------------------------------------------------------------
extern "C" void kernel_launch(void* const* d_in, const int* in_sizes, int n_in,
                              void* d_out, int out_size) {
    const float* feat   = (const float*)d_in[0];
    const float* gamma1 = (const float*)d_in[1];
    const float* beta1  = (const float*)d_in[2];
    const float* W1     = (const float*)d_in[3];
    const float* gamma2 = (const float*)d_in[4];
    const float* beta2  = (const float*)d_in[5];
    const float* W2     = (const float*)d_in[6];
    const float* Wnin   = (const float*)d_in[7];
    const int*   nbr    = (const int*)d_in[8];
    const void*  mask   = d_in[9];
    float*       out    = (float*)d_out;

    const int N = in_sizes[0] / AA;

    float *p_s1, *p_b1, *p_s2, *p_b2;
    uint32_t *p_a16, *p_m16, *p_mraw;
    cudaGetSymbolAddress((void**)&p_s1,   g_s1);
    cudaGetSymbolAddress((void**)&p_b1,   g_b1);
    cudaGetSymbolAddress((void**)&p_s2,   g_s2);
    cudaGetSymbolAddress((void**)&p_b2,   g_b2);
    cudaGetSymbolAddress((void**)&p_a16,  g_a16);
    cudaGetSymbolAddress((void**)&p_m16,  g_m16);
    cudaGetSymbolAddress((void**)&p_mraw, g_mraw);

    cudaFuncSetAttribute(k_conv<1>,
                         cudaFuncAttributeMaxDynamicSharedMemorySize, SMEMB);
    cudaFuncSetAttribute(k_conv<2>,
                         cudaFuncAttributeMaxDynamicSharedMemorySize, SMEMB);

    const int gtiles = (N + 127) / 128;
    const int wtot   = KK * 2 * 128 * 16 + KK * 4 * 128 * 16 + 2 * 128 * 16;
    const int n16    = N * 16;    // float4s in feat
    const int n32    = N * 32;    // uint2s in mid

    // prep: gather index (with fused mask detect), weight pack
    k_gidx<<<(N + 255) / 256, 256>>>(nbr, mask, N);
    k_wcvt<<<(wtot + 255) / 256, 256>>>(W1, W2, Wnin);

    // BN1: stats on fp32 feat -> folded affine -> fused apply + raw convert
    k_stats<AA, 4><<<PB, dim3(AA, 4)>>>(feat, N);
    k_fin<AA, false><<<1, dim3(AA, 8)>>>(gamma1, beta1, p_s1, p_b1, N);
    k_bn1<<<(n16 + 255) / 256, 256>>>(feat, p_s1, p_b1, n16);

    // conv1 -> g_mraw (fp16, permuted)
    k_conv<1><<<gtiles, 256, SMEMB>>>(p_a16, p_mraw, nullptr, N);

    // BN2: stats on fp16 mid -> folded affine (gamma mapped) -> apply
    k_stats16<4><<<PB, dim3(64, 4)>>>(N);
    k_fin<BB, true><<<1, dim3(BB, 8)>>>(gamma2, beta2, p_s2, p_b2, N);
    k_bn2<<<(n32 + 255) / 256, 256>>>(p_s2, p_b2, n32);

    // conv2 (NiN fused as 2 leading dense stages) -> out (write-once fp32)
    k_conv<2><<<gtiles, 256, SMEMB>>>(p_m16, nullptr, out, N);
}